// round 1
// baseline (speedup 1.0000x reference)
#include <cuda_runtime.h>

// Morphology (soft dilation):
//   y[b,c,h,w] = logsumexp_{t in 5x5}( (w[c,t] + xpad[b,c,h+i,w+j]) * BETA ) / BETA
// Factorization:
//   y = log( sum_t exp(B*w[t]) * exp(B*x[...]) ) / B
// i.e. a linear 5x5 convolution of E = exp(B*x) with per-channel kernel
// a = exp(B*w), then log()/B. Zero padding of x -> E pad value = 1.0.

#define KK 5
#define BETA 15.0f
#define CC 64
#define HH 128
#define WW 128
#define BB 4

#define TILE_H 32
#define STRIP 8                         // vertical outputs per thread
#define SM_ROWS (TILE_H + KK - 1)       // 36
#define SM_COLS (WW + KK - 1)           // 132 (132 % 32 == 4 -> no systematic conflicts)
#define NTHREADS (WW * (TILE_H / STRIP)) // 512

__global__ __launch_bounds__(NTHREADS)
void morph_soft_dilate_kernel(const float* __restrict__ x,
                              const float* __restrict__ wy,
                              float* __restrict__ out)
{
    __shared__ float sE[SM_ROWS][SM_COLS];
    __shared__ float sA[KK * KK];

    const int img   = blockIdx.y;            // b*C + c
    const int c     = img & (CC - 1);
    const int tileY = blockIdx.x * TILE_H;
    const int tid   = threadIdx.x;

    // Per-channel tap weights in exp-space (25 values, broadcast later)
    if (tid < KK * KK)
        sA[tid] = __expf(BETA * wy[c * KK * KK + tid]);

    const float* xi = x + (size_t)img * HH * WW;

    // Cooperative load of tile + halo with exp applied on the way in.
    // Out-of-bounds (zero-pad of x) -> exp(0) = 1.0f.
    for (int idx = tid; idx < SM_ROWS * SM_COLS; idx += NTHREADS) {
        int r  = idx / SM_COLS;
        int cl = idx - r * SM_COLS;
        int gr = tileY + r - 2;
        int gc = cl - 2;
        float v = 1.0f;
        if (gr >= 0 && gr < HH && gc >= 0 && gc < WW)
            v = __expf(BETA * xi[gr * WW + gc]);
        sE[r][cl] = v;
    }
    __syncthreads();

    // Pull taps into registers (warp-broadcast LDS, conflict-free)
    float a[KK * KK];
#pragma unroll
    for (int t = 0; t < KK * KK; t++) a[t] = sA[t];

    const int tx = tid & (WW - 1);        // output column (lanes consecutive -> stride-1 smem)
    const int sy = (tid >> 7) * STRIP;    // first output row of this thread's strip

    float acc[STRIP];
#pragma unroll
    for (int v = 0; v < STRIP; v++) acc[v] = 0.0f;

    // Sliding over the 12 smem rows this strip touches; each row loaded once
    // (5 values), contributing to up to 5 vertical outputs.
#pragma unroll
    for (int rr = 0; rr < STRIP + KK - 1; rr++) {
        float v0 = sE[sy + rr][tx + 0];
        float v1 = sE[sy + rr][tx + 1];
        float v2 = sE[sy + rr][tx + 2];
        float v3 = sE[sy + rr][tx + 3];
        float v4 = sE[sy + rr][tx + 4];
#pragma unroll
        for (int ky = 0; ky < KK; ky++) {
            int vo = rr - ky;
            if (vo >= 0 && vo < STRIP) {
                float p = a[ky * KK + 0] * v0;
                p = fmaf(a[ky * KK + 1], v1, p);
                p = fmaf(a[ky * KK + 2], v2, p);
                p = fmaf(a[ky * KK + 3], v3, p);
                p = fmaf(a[ky * KK + 4], v4, p);
                acc[vo] += p;
            }
        }
    }

    float* oi = out + (size_t)img * HH * WW;
    const float inv_beta = 1.0f / BETA;
#pragma unroll
    for (int v = 0; v < STRIP; v++)
        oi[(tileY + sy + v) * WW + tx] = __logf(acc[v]) * inv_beta;
}

extern "C" void kernel_launch(void* const* d_in, const int* in_sizes, int n_in,
                              void* d_out, int out_size)
{
    const float* x  = (const float*)d_in[0];   // (4, 64, 128, 128) fp32
    const float* wy = (const float*)d_in[1];   // (64, 5, 5) fp32
    float* out = (float*)d_out;                // (4, 64, 128, 128) fp32

    dim3 grid(HH / TILE_H, BB * CC);           // (4, 256) = 1024 blocks
    morph_soft_dilate_kernel<<<grid, NTHREADS>>>(x, wy, out);
}

// round 3
// speedup vs baseline: 1.6334x; 1.6334x over previous
#include <cuda_runtime.h>

// Soft 5x5 dilation:  y = logsumexp((w + patch)*B)/B
// Factored:           y = log2( conv5x5( exp2(B*log2e*x), exp2(B*log2e*w) ) ) * (ln2/B)
// Zero-pad of x -> pad value exp(0) = 1.0 in exp-space.

#define KK 5
#define BETA 15.0f
#define CC 64
#define HH 128
#define WW 128
#define BB 4

#define TILE_H 32
#define SROWS (TILE_H + 4)      // 36
#define SCOLS 132               // smem col = input col + 2 ; halo cols 0,1,130,131
#define NT 256

#define B_LOG2E (BETA * 1.44269504f)    // fold into exp2
#define LN2_OVER_B (0.69314718f / BETA) // fold into log2

__device__ __forceinline__ float fast_ex2(float v) {
    float r;
    asm("ex2.approx.ftz.f32 %0, %1;" : "=f"(r) : "f"(v));
    return r;
}
__device__ __forceinline__ float fast_lg2(float v) {
    float r;
    asm("lg2.approx.ftz.f32 %0, %1;" : "=f"(r) : "f"(v));
    return r;
}

__global__ __launch_bounds__(NT, 3)
void morph_soft_dilate_kernel(const float* __restrict__ x,
                              const float* __restrict__ wy,
                              float* __restrict__ out)
{
    __shared__ float sE[SROWS][SCOLS];   // 36*132*4 = 19008 B (row stride 528B, 16B aligned)
    __shared__ float sA[32];

    const int img   = blockIdx.y;          // b*C + c
    const int c     = img & (CC - 1);
    const int tileY = blockIdx.x * TILE_H;
    const int t     = threadIdx.x;

    // taps in exp space
    if (t < KK * KK)
        sA[t] = fast_ex2(B_LOG2E * wy[c * KK * KK + t]);

    // blanket-fill smem with pad value 1.0 (covers all halo cases, no predication later)
    {
        float4* sp = (float4*)&sE[0][0];
        const float4 ones = make_float4(1.f, 1.f, 1.f, 1.f);
        #pragma unroll
        for (int i = 0; i < 5; i++) {
            int idx = t + i * NT;
            if (idx < (SROWS * SCOLS) / 4) sp[idx] = ones;
        }
    }
    __syncthreads();

    // vectorized tile load with exp applied; only in-bounds elements written
    {
        const float* xi = x + (size_t)img * (HH * WW);
        const int lane = t & 31;        // col group: global cols 4*lane..4*lane+3
        const int r0   = t >> 5;        // 8 rows per pass
        #pragma unroll
        for (int p = 0; p < 5; p++) {
            int r  = r0 + 8 * p;
            int gr = tileY + r - 2;
            if (r < SROWS && gr >= 0 && gr < HH) {
                float4 v = *(const float4*)&xi[gr * WW + 4 * lane];
                float2 e01 = make_float2(fast_ex2(B_LOG2E * v.x), fast_ex2(B_LOG2E * v.y));
                float2 e23 = make_float2(fast_ex2(B_LOG2E * v.z), fast_ex2(B_LOG2E * v.w));
                *(float2*)&sE[r][4 * lane + 2] = e01;   // 8B aligned
                *(float2*)&sE[r][4 * lane + 4] = e23;
            }
        }
    }
    __syncthreads();

    // taps to registers (warp-broadcast reads)
    float a[KK * KK];
    #pragma unroll
    for (int i = 0; i < KK * KK; i++) a[i] = sA[i];

    const int cg = t & 31;          // output cols 4*cg .. 4*cg+3
    const int sy = (t >> 5) * 4;    // output rows tileY+sy .. +3

    float acc[4][4];
    #pragma unroll
    for (int v = 0; v < 4; v++)
        #pragma unroll
        for (int j = 0; j < 4; j++) acc[v][j] = 0.0f;

    // slide over the 8 smem rows this 4x4 patch touches; each row: 2x LDS.128
    // (window smem cols 4cg..4cg+7 exactly == input cols 4cg-2..4cg+5, 16B aligned)
    #pragma unroll
    for (int rr = 0; rr < 8; rr++) {
        float4 f0 = *(const float4*)&sE[sy + rr][4 * cg];
        float4 f1 = *(const float4*)&sE[sy + rr][4 * cg + 4];
        float f[8] = {f0.x, f0.y, f0.z, f0.w, f1.x, f1.y, f1.z, f1.w};
        #pragma unroll
        for (int ky = 0; ky < KK; ky++) {
            int vo = rr - ky;
            if (vo >= 0 && vo < 4) {
                #pragma unroll
                for (int j = 0; j < 4; j++) {
                    float s = acc[vo][j];
                    #pragma unroll
                    for (int kx = 0; kx < KK; kx++)
                        s = fmaf(a[ky * KK + kx], f[j + kx], s);
                    acc[vo][j] = s;
                }
            }
        }
    }

    // log + vectorized store
    float* oi = out + (size_t)img * (HH * WW);
    #pragma unroll
    for (int v = 0; v < 4; v++) {
        float4 o;
        o.x = fast_lg2(acc[v][0]) * LN2_OVER_B;
        o.y = fast_lg2(acc[v][1]) * LN2_OVER_B;
        o.z = fast_lg2(acc[v][2]) * LN2_OVER_B;
        o.w = fast_lg2(acc[v][3]) * LN2_OVER_B;
        *(float4*)&oi[(tileY + sy + v) * WW + 4 * cg] = o;
    }
}

extern "C" void kernel_launch(void* const* d_in, const int* in_sizes, int n_in,
                              void* d_out, int out_size)
{
    const float* x  = (const float*)d_in[0];   // (4, 64, 128, 128) fp32
    const float* wy = (const float*)d_in[1];   // (64, 5, 5) fp32
    float* out = (float*)d_out;                // (4, 64, 128, 128) fp32

    dim3 grid(HH / TILE_H, BB * CC);           // (4, 256) = 1024 blocks
    morph_soft_dilate_kernel<<<grid, NT>>>(x, wy, out);
}

// round 4
// speedup vs baseline: 1.6457x; 1.0075x over previous
#include <cuda_runtime.h>

// Soft 5x5 dilation:  y = logsumexp((w + patch)*B)/B
// Factored:  y = log2( conv5x5( exp2(c*x), exp2(c*w) ) ) * (ln2/B),  c = B*log2e
// Zero-pad of x -> pad value 1.0 in exp-space.
// Conv inner loop uses packed fma.rn.f32x2 (two output columns per op).

#define KK 5
#define BETA 15.0f
#define CC 64
#define HH 128
#define WW 128
#define BB 4

#define TILE_H 16
#define SROWS (TILE_H + 4)      // 20
#define SCOLS 132               // smem col = input col + 2
#define NT 128

#define B_LOG2E (BETA * 1.44269504f)
#define LN2_OVER_B (0.69314718f / BETA)

__device__ __forceinline__ float fast_ex2(float v) {
    float r; asm("ex2.approx.ftz.f32 %0, %1;" : "=f"(r) : "f"(v)); return r;
}
__device__ __forceinline__ float fast_lg2(float v) {
    float r; asm("lg2.approx.ftz.f32 %0, %1;" : "=f"(r) : "f"(v)); return r;
}

union F2U { float2 f; unsigned long long u; };
__device__ __forceinline__ float2 ffma2(float2 a, float2 b, float2 c) {
    F2U A, B, C, D; A.f = a; B.f = b; C.f = c;
    asm("fma.rn.f32x2 %0, %1, %2, %3;" : "=l"(D.u) : "l"(A.u), "l"(B.u), "l"(C.u));
    return D.f;
}

__global__ __launch_bounds__(NT, 5)
void morph_soft_dilate_kernel(const float* __restrict__ x,
                              const float* __restrict__ wy,
                              float* __restrict__ out)
{
    __shared__ float sE[SROWS][SCOLS];   // 20*132*4 = 10560 B
    __shared__ float sA[32];

    const int img   = blockIdx.y;          // b*C + c
    const int c     = img & (CC - 1);
    const int tileY = blockIdx.x * TILE_H;
    const int t     = threadIdx.x;

    if (t < KK * KK)
        sA[t] = fast_ex2(B_LOG2E * wy[c * KK * KK + t]);

    // blanket-fill smem with pad value 1.0
    {
        float4* sp = (float4*)&sE[0][0];
        const float4 ones = make_float4(1.f, 1.f, 1.f, 1.f);
        #pragma unroll
        for (int i = 0; i < 6; i++) {
            int idx = t + i * NT;
            if (idx < (SROWS * SCOLS) / 4) sp[idx] = ones;
        }
    }
    __syncthreads();

    // vectorized tile load with exp applied
    {
        const float* xi = x + (size_t)img * (HH * WW);
        const int lane = t & 31;        // cols 4*lane..4*lane+3
        const int r0   = t >> 5;        // 4 rows per pass
        #pragma unroll
        for (int p = 0; p < 5; p++) {
            int r  = r0 + 4 * p;
            int gr = tileY + r - 2;
            if (gr >= 0 && gr < HH) {
                float4 v = *(const float4*)&xi[gr * WW + 4 * lane];
                float2 e01 = make_float2(fast_ex2(B_LOG2E * v.x), fast_ex2(B_LOG2E * v.y));
                float2 e23 = make_float2(fast_ex2(B_LOG2E * v.z), fast_ex2(B_LOG2E * v.w));
                *(float2*)&sE[r][4 * lane + 2] = e01;
                *(float2*)&sE[r][4 * lane + 4] = e23;
            }
        }
    }
    __syncthreads();

    // taps duplicated into both f32x2 lanes
    float2 a2[KK * KK];
    #pragma unroll
    for (int i = 0; i < KK * KK; i++) { float v = sA[i]; a2[i] = make_float2(v, v); }

    const int cg = t & 31;          // output cols 4*cg .. 4*cg+3
    const int sy = (t >> 5) * 4;    // output rows tileY+sy .. +3

    float2 acc01[4], acc23[4];
    #pragma unroll
    for (int v = 0; v < 4; v++) {
        acc01[v] = make_float2(0.f, 0.f);
        acc23[v] = make_float2(0.f, 0.f);
    }

    // 8 smem rows feed this thread's 4x4 patch; per row: 2x LDS.128,
    // 7 adjacent pairs (4 free from the loads, 3 built), FFMA2 throughout.
    #pragma unroll
    for (int rr = 0; rr < 8; rr++) {
        float4 q0 = *(const float4*)&sE[sy + rr][4 * cg];
        float4 q1 = *(const float4*)&sE[sy + rr][4 * cg + 4];
        float2 p[7];
        p[0] = make_float2(q0.x, q0.y);
        p[1] = make_float2(q0.y, q0.z);
        p[2] = make_float2(q0.z, q0.w);
        p[3] = make_float2(q0.w, q1.x);
        p[4] = make_float2(q1.x, q1.y);
        p[5] = make_float2(q1.y, q1.z);
        p[6] = make_float2(q1.z, q1.w);
        #pragma unroll
        for (int ky = 0; ky < KK; ky++) {
            int vo = rr - ky;
            if (vo >= 0 && vo < 4) {
                #pragma unroll
                for (int kx = 0; kx < KK; kx++) {
                    acc01[vo] = ffma2(a2[ky * KK + kx], p[kx],     acc01[vo]);
                    acc23[vo] = ffma2(a2[ky * KK + kx], p[kx + 2], acc23[vo]);
                }
            }
        }
    }

    float* oi = out + (size_t)img * (HH * WW);
    #pragma unroll
    for (int v = 0; v < 4; v++) {
        float4 o;
        o.x = fast_lg2(acc01[v].x) * LN2_OVER_B;
        o.y = fast_lg2(acc01[v].y) * LN2_OVER_B;
        o.z = fast_lg2(acc23[v].x) * LN2_OVER_B;
        o.w = fast_lg2(acc23[v].y) * LN2_OVER_B;
        *(float4*)&oi[(tileY + sy + v) * WW + 4 * cg] = o;
    }
}

extern "C" void kernel_launch(void* const* d_in, const int* in_sizes, int n_in,
                              void* d_out, int out_size)
{
    const float* x  = (const float*)d_in[0];   // (4, 64, 128, 128) fp32
    const float* wy = (const float*)d_in[1];   // (64, 5, 5) fp32
    float* out = (float*)d_out;                // (4, 64, 128, 128) fp32

    dim3 grid(HH / TILE_H, BB * CC);           // (8, 256) = 2048 blocks
    morph_soft_dilate_kernel<<<grid, NT>>>(x, wy, out);
}

// round 5
// speedup vs baseline: 1.9552x; 1.1881x over previous
#include <cuda_runtime.h>

// Soft 5x5 dilation:  y = logsumexp((w + patch)*B)/B
// Factored:  y = log2( conv5x5( exp2(c*x), exp2(c*w) ) ) * (ln2/B),  c = B*log2e
// Zero-pad of x -> pad value 1.0 in exp-space.
// Conv inner loop: packed fma.rn.f32x2, two output columns per op.

#define KK 5
#define BETA 15.0f
#define CC 64
#define HH 128
#define WW 128
#define BB 4

#define TILE_H 16
#define SROWS (TILE_H + 4)      // 20
#define SCOLS 132               // smem col = input col + 2
#define NT 128

#define B_LOG2E (BETA * 1.44269504f)
#define LN2_OVER_B (0.69314718f / BETA)

__device__ __forceinline__ float fast_ex2(float v) {
    float r; asm("ex2.approx.ftz.f32 %0, %1;" : "=f"(r) : "f"(v)); return r;
}
__device__ __forceinline__ float fast_lg2(float v) {
    float r; asm("lg2.approx.ftz.f32 %0, %1;" : "=f"(r) : "f"(v)); return r;
}

union F2U { float2 f; unsigned long long u; };
__device__ __forceinline__ float2 ffma2(float2 a, float2 b, float2 c) {
    F2U A, B, C, D; A.f = a; B.f = b; C.f = c;
    asm("fma.rn.f32x2 %0, %1, %2, %3;" : "=l"(D.u) : "l"(A.u), "l"(B.u), "l"(C.u));
    return D.f;
}

__global__ __launch_bounds__(NT, 8)
void morph_soft_dilate_kernel(const float* __restrict__ x,
                              const float* __restrict__ wy,
                              float* __restrict__ out)
{
    __shared__ float sE[SROWS][SCOLS];   // 20*132*4 = 10560 B
    __shared__ float sA[32];

    const int img   = blockIdx.y;          // b*C + c
    const int c     = img & (CC - 1);
    const int tileY = blockIdx.x * TILE_H;
    const int t     = threadIdx.x;
    const int lane  = t & 31;
    const int r0    = t >> 5;

    const float* xi = x + (size_t)img * (HH * WW);

    // ── Hoisted, predicated global loads: 5 LDG.128 in flight (MLP=5) ──
    float4 v[5];
    bool ok[5];
    #pragma unroll
    for (int p = 0; p < 5; p++) {
        int gr = tileY + r0 + 4 * p - 2;
        ok[p] = (gr >= 0) && (gr < HH);
        if (ok[p]) v[p] = *(const float4*)&xi[gr * WW + 4 * lane];
    }

    // ── Setup overlapping the LDG latency ──
    // taps in exp space
    if (t < KK * KK)
        sA[t] = fast_ex2(B_LOG2E * wy[c * KK * KK + t]);

    // halo columns 0,1,130,131 for all 20 rows (40 threads, 2 cols each)
    if (t < 40) {
        int r  = t >> 1;
        int cb = (t & 1) ? 130 : 0;
        sE[r][cb]     = 1.0f;
        sE[r][cb + 1] = 1.0f;
    }
    // pad rows: only boundary blocks (rows 0,1 at top tile; rows 18,19 at bottom)
    {
        float4* sp = (float4*)&sE[0][0];
        const float4 ones = make_float4(1.f, 1.f, 1.f, 1.f);
        if (tileY == 0 && t < 66)               sp[t] = ones;        // rows 0,1
        if (tileY == HH - TILE_H && t < 66)     sp[594 + t] = ones;  // rows 18,19 (18*132/4=594)
    }

    // ── Convert + store to smem ──
    #pragma unroll
    for (int p = 0; p < 5; p++) {
        if (ok[p]) {
            int r = r0 + 4 * p;
            float2 e01 = make_float2(fast_ex2(B_LOG2E * v[p].x), fast_ex2(B_LOG2E * v[p].y));
            float2 e23 = make_float2(fast_ex2(B_LOG2E * v[p].z), fast_ex2(B_LOG2E * v[p].w));
            *(float2*)&sE[r][4 * lane + 2] = e01;
            *(float2*)&sE[r][4 * lane + 4] = e23;
        }
    }
    __syncthreads();

    // taps duplicated into both f32x2 lanes
    float2 a2[KK * KK];
    #pragma unroll
    for (int i = 0; i < KK * KK; i++) { float w0 = sA[i]; a2[i] = make_float2(w0, w0); }

    const int cg = lane;            // output cols 4*cg .. 4*cg+3
    const int sy = r0 * 4;          // output rows tileY+sy .. +3

    float2 acc01[4], acc23[4];
    #pragma unroll
    for (int q = 0; q < 4; q++) {
        acc01[q] = make_float2(0.f, 0.f);
        acc23[q] = make_float2(0.f, 0.f);
    }

    // 8 smem rows feed the 4x4 patch; per row: 2x LDS.128, packed FFMA2
    #pragma unroll
    for (int rr = 0; rr < 8; rr++) {
        float4 q0 = *(const float4*)&sE[sy + rr][4 * cg];
        float4 q1 = *(const float4*)&sE[sy + rr][4 * cg + 4];
        float2 p[7];
        p[0] = make_float2(q0.x, q0.y);
        p[1] = make_float2(q0.y, q0.z);
        p[2] = make_float2(q0.z, q0.w);
        p[3] = make_float2(q0.w, q1.x);
        p[4] = make_float2(q1.x, q1.y);
        p[5] = make_float2(q1.y, q1.z);
        p[6] = make_float2(q1.z, q1.w);
        #pragma unroll
        for (int ky = 0; ky < KK; ky++) {
            int vo = rr - ky;
            if (vo >= 0 && vo < 4) {
                #pragma unroll
                for (int kx = 0; kx < KK; kx++) {
                    acc01[vo] = ffma2(a2[ky * KK + kx], p[kx],     acc01[vo]);
                    acc23[vo] = ffma2(a2[ky * KK + kx], p[kx + 2], acc23[vo]);
                }
            }
        }
    }

    float* oi = out + (size_t)img * (HH * WW);
    #pragma unroll
    for (int q = 0; q < 4; q++) {
        float4 o;
        o.x = fast_lg2(acc01[q].x) * LN2_OVER_B;
        o.y = fast_lg2(acc01[q].y) * LN2_OVER_B;
        o.z = fast_lg2(acc23[q].x) * LN2_OVER_B;
        o.w = fast_lg2(acc23[q].y) * LN2_OVER_B;
        *(float4*)&oi[(tileY + sy + q) * WW + 4 * cg] = o;
    }
}

extern "C" void kernel_launch(void* const* d_in, const int* in_sizes, int n_in,
                              void* d_out, int out_size)
{
    const float* x  = (const float*)d_in[0];   // (4, 64, 128, 128) fp32
    const float* wy = (const float*)d_in[1];   // (64, 5, 5) fp32
    float* out = (float*)d_out;                // (4, 64, 128, 128) fp32

    dim3 grid(HH / TILE_H, BB * CC);           // (8, 256) = 2048 blocks
    morph_soft_dilate_kernel<<<grid, NT>>>(x, wy, out);
}